// round 2
// baseline (speedup 1.0000x reference)
#include <cuda_runtime.h>
#include <cuda_bf16.h>
#include <cstdint>

// ---------------------------------------------------------------------------
// Problem constants
// ---------------------------------------------------------------------------
#define M_DIM 4096      // out features
#define K_DIM 4096      // in features
#define N_DIM 8192      // cols of x / out
#define BM 128          // CTA tile M
#define BN 256          // CTA tile N
#define BK 32           // K per stage
#define NPASS 3         // Whi*Xhi, Whi*Xlo, Wlo*Xhi
#define KT_PER_PASS (K_DIM / BK)      // 128
#define ITERS (NPASS * KT_PER_PASS)   // 384
#define STAGES 4
#define THREADS 256

// smem: rows padded 64B -> 80B for conflict-free ldmatrix
#define ROW_B 80
#define A_STAGE_B (BM * ROW_B)            // 10240
#define B_STAGE_B (BN * ROW_B)            // 20480
#define STAGE_B (A_STAGE_B + B_STAGE_B)   // 30720
#define SMEM_TOTAL (STAGES * STAGE_B)     // 122880

// ---------------------------------------------------------------------------
// Device scratch (allocation-free rule: __device__ globals)
// Pack layout (k-major 32-wide panels): elem(m,k) -> [(k/32)*DIM + m]*32 + k%32
// ---------------------------------------------------------------------------
__device__ float          g_Wdense[(size_t)M_DIM * K_DIM];   // 64 MB
__device__ unsigned short g_Whi[(size_t)M_DIM * K_DIM];      // 32 MB
__device__ unsigned short g_Wlo[(size_t)M_DIM * K_DIM];      // 32 MB
__device__ unsigned short g_Xhi[(size_t)N_DIM * K_DIM];      // 64 MB
__device__ unsigned short g_Xlo[(size_t)N_DIM * K_DIM];      // 64 MB

// ---------------------------------------------------------------------------
// PTX helpers (sm_80-base ISA only: cp.async, ldmatrix, mma.sync)
// ---------------------------------------------------------------------------
__device__ __forceinline__ uint32_t smem_u32(const void* p) {
    uint32_t a;
    asm("{ .reg .u64 t; cvta.to.shared.u64 t, %1; cvt.u32.u64 %0, t; }" : "=r"(a) : "l"(p));
    return a;
}

__device__ __forceinline__ void cp16(uint32_t dst, const void* src) {
    asm volatile("cp.async.cg.shared.global [%0], [%1], 16;" :: "r"(dst), "l"(src));
}

#define CP_COMMIT() asm volatile("cp.async.commit_group;" ::: "memory")
#define CP_WAIT2()  asm volatile("cp.async.wait_group 2;" ::: "memory")

__device__ __forceinline__ void ldsm4(uint32_t r[4], uint32_t addr) {
    asm volatile("ldmatrix.sync.aligned.m8n8.x4.shared.b16 {%0,%1,%2,%3}, [%4];"
        : "=r"(r[0]), "=r"(r[1]), "=r"(r[2]), "=r"(r[3]) : "r"(addr));
}

__device__ __forceinline__ void mma16816(float d[4], const uint32_t a[4],
                                         uint32_t b0, uint32_t b1) {
    asm volatile(
        "mma.sync.aligned.m16n8k16.row.col.f32.bf16.bf16.f32 "
        "{%0,%1,%2,%3}, {%4,%5,%6,%7}, {%8,%9}, {%0,%1,%2,%3};"
        : "+f"(d[0]), "+f"(d[1]), "+f"(d[2]), "+f"(d[3])
        : "r"(a[0]), "r"(a[1]), "r"(a[2]), "r"(a[3]), "r"(b0), "r"(b1));
}

// ---------------------------------------------------------------------------
// Preprocessing
// ---------------------------------------------------------------------------
__global__ void clear_kernel() {
    size_t n4 = ((size_t)M_DIM * K_DIM) / 4;
    float4 z = make_float4(0.f, 0.f, 0.f, 0.f);
    float4* p = reinterpret_cast<float4*>(g_Wdense);
    for (size_t i = (size_t)blockIdx.x * blockDim.x + threadIdx.x; i < n4;
         i += (size_t)gridDim.x * blockDim.x)
        p[i] = z;
}

__global__ void scatter_kernel(const int* __restrict__ rows, const int* __restrict__ cols,
                               const float* __restrict__ vals, int nnz) {
    int i = blockIdx.x * blockDim.x + threadIdx.x;
    if (i < nnz)
        atomicAdd(&g_Wdense[(size_t)rows[i] * K_DIM + cols[i]], vals[i]);
}

__global__ void packW_kernel() {
    size_t t = (size_t)blockIdx.x * blockDim.x + threadIdx.x;  // one float4 = 4 k-elems
    size_t n4 = ((size_t)M_DIM * K_DIM) / 4;
    if (t >= n4) return;
    int m = (int)(t >> 10);          // K_DIM/4 = 1024 float4 per m-row
    int k = (int)(t & 1023) * 4;
    float4 w = reinterpret_cast<const float4*>(g_Wdense)[t];
    size_t dst = ((size_t)(k >> 5) * M_DIM + m) * 32 + (k & 31);
    float wv[4] = {w.x, w.y, w.z, w.w};
    ushort4 hi4, lo4;
    unsigned short* hp = &hi4.x;
    unsigned short* lp = &lo4.x;
#pragma unroll
    for (int j = 0; j < 4; ++j) {
        __nv_bfloat16 hi = __float2bfloat16(wv[j]);
        __nv_bfloat16 lo = __float2bfloat16(wv[j] - __bfloat162float(hi));
        hp[j] = __bfloat16_as_ushort(hi);
        lp[j] = __bfloat16_as_ushort(lo);
    }
    *reinterpret_cast<ushort4*>(&g_Whi[dst]) = hi4;
    *reinterpret_cast<ushort4*>(&g_Wlo[dst]) = lo4;
}

// Transpose x[K,N] -> packed xT panels
__global__ void packX_kernel(const float* __restrict__ x) {
    __shared__ float sh[64 * 33];
    int k0 = blockIdx.x * 64;   // gridDim.x = K/64 = 64
    int n0 = blockIdx.y * 32;   // gridDim.y = N/32 = 256
    int t = threadIdx.x;        // 256 threads
#pragma unroll
    for (int i = 0; i < 8; ++i) {
        int idx = i * 256 + t;
        int kk = idx >> 5, nl = idx & 31;
        sh[kk * 33 + nl] = x[(size_t)(k0 + kk) * N_DIM + n0 + nl];
    }
    __syncthreads();
#pragma unroll
    for (int j = 0; j < 8; ++j) {
        int idx = j * 256 + t;
        int nl = idx >> 6, kk = idx & 63;
        int n = n0 + nl;
        int k = k0 + kk;
        float v = sh[kk * 33 + nl];
        __nv_bfloat16 hi = __float2bfloat16(v);
        __nv_bfloat16 lo = __float2bfloat16(v - __bfloat162float(hi));
        size_t dst = ((size_t)(k >> 5) * N_DIM + n) * 32 + (k & 31);
        g_Xhi[dst] = __bfloat16_as_ushort(hi);
        g_Xlo[dst] = __bfloat16_as_ushort(lo);
    }
}

// ---------------------------------------------------------------------------
// Main GEMM: out = Whi*Xhi + Whi*Xlo + Wlo*Xhi   (K_eff = 3*4096)
// 128x256x32 CTA tile, 8 warps (2m x 4n), warp tile 64x64, 4-stage cp.async.
// ---------------------------------------------------------------------------
__global__ void __launch_bounds__(THREADS, 1) gemm3_kernel(float* __restrict__ out) {
    extern __shared__ __align__(128) char smem[];
    const uint32_t sb = smem_u32(smem);
    const int tid = threadIdx.x;
    const int lane = tid & 31;
    const int wid = tid >> 5;
    const int wm = (wid >> 2) * 64;   // warp m offset (0/64)
    const int wn = (wid & 3) * 64;    // warp n offset (0/64/128/192)
    const int m0 = blockIdx.x * BM;
    const int n0 = blockIdx.y * BN;

    float acc[4][8][4];
#pragma unroll
    for (int i = 0; i < 4; ++i)
#pragma unroll
        for (int j = 0; j < 8; ++j)
#pragma unroll
            for (int r = 0; r < 4; ++r) acc[i][j][r] = 0.f;

    // per-lane ldmatrix offsets (bytes)
    // A 16x16 tile: lanes 0-15 -> rows, lanes 16-31 -> rows with +16B (k=8..15)
    const uint32_t a_lane_off =
        (uint32_t)((wm + (lane & 15)) * ROW_B + (lane >> 4) * 16);
    // B 16(n)x16(k): lanes 0-7 n0-7@k0, 8-15 n0-7@k8, 16-23 n8-15@k0, 24-31 n8-15@k8
    const uint32_t b_lane_off =
        (uint32_t)((wn + (lane & 7) + ((lane >> 4) & 1) * 8) * ROW_B +
                   ((lane >> 3) & 1) * 16);

    const char* const Apass[NPASS] = {(const char*)g_Whi, (const char*)g_Whi,
                                      (const char*)g_Wlo};
    const char* const Bpass[NPASS] = {(const char*)g_Xhi, (const char*)g_Xlo,
                                      (const char*)g_Xhi};

    auto load_stage = [&](int it, int s) {
        int pass = it / KT_PER_PASS;
        int kt = it - pass * KT_PER_PASS;
        const char* asrc = Apass[pass] + ((size_t)kt * M_DIM + m0) * 64;
        const char* bsrc = Bpass[pass] + ((size_t)kt * N_DIM + n0) * 64;
        uint32_t As = sb + s * STAGE_B;
        uint32_t Bs = As + A_STAGE_B;
#pragma unroll
        for (int j = 0; j < 2; ++j) {   // A: 512 x 16B chunks
            int c = tid + j * THREADS;
            cp16(As + (uint32_t)((c >> 2) * ROW_B + (c & 3) * 16), asrc + (size_t)c * 16);
        }
#pragma unroll
        for (int j = 0; j < 4; ++j) {   // B: 1024 x 16B chunks
            int c = tid + j * THREADS;
            cp16(Bs + (uint32_t)((c >> 2) * ROW_B + (c & 3) * 16), bsrc + (size_t)c * 16);
        }
    };

    auto compute = [&](int s) {
        const uint32_t As = sb + s * STAGE_B + a_lane_off;
        const uint32_t Bs = sb + s * STAGE_B + A_STAGE_B + b_lane_off;
#pragma unroll
        for (int ks = 0; ks < 2; ++ks) {
            uint32_t a[4][4], b[4][4];
#pragma unroll
            for (int mi = 0; mi < 4; ++mi)
                ldsm4(a[mi], As + mi * (16 * ROW_B) + ks * 32);
#pragma unroll
            for (int nj = 0; nj < 4; ++nj)
                ldsm4(b[nj], Bs + nj * (16 * ROW_B) + ks * 32);
#pragma unroll
            for (int mi = 0; mi < 4; ++mi)
#pragma unroll
                for (int nj = 0; nj < 4; ++nj) {
                    mma16816(acc[mi][2 * nj], a[mi], b[nj][0], b[nj][1]);
                    mma16816(acc[mi][2 * nj + 1], a[mi], b[nj][2], b[nj][3]);
                }
        }
    };

    // prologue: fill 3 stages
#pragma unroll
    for (int s = 0; s < STAGES - 1; ++s) {
        load_stage(s, s);
        CP_COMMIT();
    }

    for (int it = 0; it < ITERS; ++it) {
        CP_WAIT2();            // own groups <= it complete
        __syncthreads();       // cross-thread visibility + smem reuse safety
        if (it + 3 < ITERS) load_stage(it + 3, (it + 3) & (STAGES - 1));
        CP_COMMIT();           // always commit (possibly empty) to keep count math
        compute(it & (STAGES - 1));
    }

    // epilogue: direct fp32 stores (each element owned by exactly one thread)
#pragma unroll
    for (int mi = 0; mi < 4; ++mi) {
        int row = m0 + wm + mi * 16 + (lane >> 2);
#pragma unroll
        for (int ni = 0; ni < 8; ++ni) {
            int col = n0 + wn + ni * 8 + (lane & 3) * 2;
            float2* p0 = reinterpret_cast<float2*>(out + (size_t)row * N_DIM + col);
            float2* p1 = reinterpret_cast<float2*>(out + (size_t)(row + 8) * N_DIM + col);
            *p0 = make_float2(acc[mi][ni][0], acc[mi][ni][1]);
            *p1 = make_float2(acc[mi][ni][2], acc[mi][ni][3]);
        }
    }
}

// ---------------------------------------------------------------------------
// Launch
// ---------------------------------------------------------------------------
extern "C" void kernel_launch(void* const* d_in, const int* in_sizes, int n_in,
                              void* d_out, int out_size) {
    const int*   rows = (const int*)d_in[0];
    const int*   cols = (const int*)d_in[1];
    const float* vals = (const float*)d_in[2];
    const float* x    = (const float*)d_in[3];
    float* out = (float*)d_out;
    int nnz = in_sizes[0];

    clear_kernel<<<2048, 256>>>();
    scatter_kernel<<<(nnz + 255) / 256, 256>>>(rows, cols, vals, nnz);
    packW_kernel<<<(int)(((size_t)M_DIM * K_DIM / 4 + 255) / 256), 256>>>();
    packX_kernel<<<dim3(K_DIM / 64, N_DIM / 32), 256>>>(x);

    static int smem_set = 0;
    if (!smem_set) {
        cudaFuncSetAttribute(gemm3_kernel, cudaFuncAttributeMaxDynamicSharedMemorySize,
                             SMEM_TOTAL);
        smem_set = 1;
    }
    gemm3_kernel<<<dim3(M_DIM / BM, N_DIM / BN), THREADS, SMEM_TOTAL>>>(out);
}

// round 3
// speedup vs baseline: 3.0913x; 3.0913x over previous
#include <cuda_runtime.h>
#include <cuda_fp16.h>
#include <cstdint>

// ---------------------------------------------------------------------------
// Problem constants
// ---------------------------------------------------------------------------
#define M_DIM 4096      // out features
#define K_DIM 4096      // in features
#define N_DIM 8192      // cols of x / out
#define BM 128          // CTA tile M
#define BN 256          // CTA tile N
#define BK 32           // K per stage
#define ITERS (K_DIM / BK)   // 128 (single fp16 pass)
#define STAGES 4
#define THREADS 512

// smem: rows padded 64B -> 80B for conflict-free ldmatrix
#define ROW_B 80
#define A_STAGE_B (BM * ROW_B)            // 10240
#define B_STAGE_B (BN * ROW_B)            // 20480
#define STAGE_B (A_STAGE_B + B_STAGE_B)   // 30720
#define SMEM_TOTAL (STAGES * STAGE_B)     // 122880

// ---------------------------------------------------------------------------
// Device scratch (allocation-free rule: __device__ globals)
// Pack layout (k-major 32-wide panels): elem(m,k) -> [(k/32)*DIM + m]*32 + k%32
// ---------------------------------------------------------------------------
__device__ float          g_Wdense[(size_t)M_DIM * K_DIM];   // 64 MB (exact duplicate sums)
__device__ unsigned short g_Wh[(size_t)M_DIM * K_DIM];       // 32 MB fp16 packed panels
__device__ unsigned short g_Xh[(size_t)N_DIM * K_DIM];       // 64 MB fp16 packed xT panels

// ---------------------------------------------------------------------------
// PTX helpers (sm_80-base ISA only: cp.async, ldmatrix, mma.sync)
// ---------------------------------------------------------------------------
__device__ __forceinline__ uint32_t smem_u32(const void* p) {
    uint32_t a;
    asm("{ .reg .u64 t; cvta.to.shared.u64 t, %1; cvt.u32.u64 %0, t; }" : "=r"(a) : "l"(p));
    return a;
}

__device__ __forceinline__ void cp16(uint32_t dst, const void* src) {
    asm volatile("cp.async.cg.shared.global [%0], [%1], 16;" :: "r"(dst), "l"(src));
}

#define CP_COMMIT() asm volatile("cp.async.commit_group;" ::: "memory")
#define CP_WAIT2()  asm volatile("cp.async.wait_group 2;" ::: "memory")

__device__ __forceinline__ void ldsm4(uint32_t r[4], uint32_t addr) {
    asm volatile("ldmatrix.sync.aligned.m8n8.x4.shared.b16 {%0,%1,%2,%3}, [%4];"
        : "=r"(r[0]), "=r"(r[1]), "=r"(r[2]), "=r"(r[3]) : "r"(addr));
}

__device__ __forceinline__ void mma16816(float d[4], const uint32_t a[4],
                                         uint32_t b0, uint32_t b1) {
    asm volatile(
        "mma.sync.aligned.m16n8k16.row.col.f32.f16.f16.f32 "
        "{%0,%1,%2,%3}, {%4,%5,%6,%7}, {%8,%9}, {%0,%1,%2,%3};"
        : "+f"(d[0]), "+f"(d[1]), "+f"(d[2]), "+f"(d[3])
        : "r"(a[0]), "r"(a[1]), "r"(a[2]), "r"(a[3]), "r"(b0), "r"(b1));
}

// ---------------------------------------------------------------------------
// Preprocessing
// ---------------------------------------------------------------------------
__global__ void clear_kernel() {
    size_t n4 = ((size_t)M_DIM * K_DIM) / 4;
    float4 z = make_float4(0.f, 0.f, 0.f, 0.f);
    float4* p = reinterpret_cast<float4*>(g_Wdense);
    for (size_t i = (size_t)blockIdx.x * blockDim.x + threadIdx.x; i < n4;
         i += (size_t)gridDim.x * blockDim.x)
        p[i] = z;
}

__global__ void scatter_kernel(const int* __restrict__ rows, const int* __restrict__ cols,
                               const float* __restrict__ vals, int nnz) {
    int i = blockIdx.x * blockDim.x + threadIdx.x;
    if (i < nnz)
        atomicAdd(&g_Wdense[(size_t)rows[i] * K_DIM + cols[i]], vals[i]);
}

__global__ void packW_kernel() {
    size_t t = (size_t)blockIdx.x * blockDim.x + threadIdx.x;  // one float4 = 4 k-elems
    size_t n4 = ((size_t)M_DIM * K_DIM) / 4;
    if (t >= n4) return;
    int m = (int)(t >> 10);          // K_DIM/4 = 1024 float4 per m-row
    int k = (int)(t & 1023) * 4;
    float4 w = reinterpret_cast<const float4*>(g_Wdense)[t];
    size_t dst = ((size_t)(k >> 5) * M_DIM + m) * 32 + (k & 31);
    ushort4 h4;
    h4.x = __half_as_ushort(__float2half_rn(w.x));
    h4.y = __half_as_ushort(__float2half_rn(w.y));
    h4.z = __half_as_ushort(__float2half_rn(w.z));
    h4.w = __half_as_ushort(__float2half_rn(w.w));
    *reinterpret_cast<ushort4*>(&g_Wh[dst]) = h4;
}

// Transpose x[K,N] -> packed xT fp16 panels
__global__ void packX_kernel(const float* __restrict__ x) {
    __shared__ float sh[64 * 33];
    int k0 = blockIdx.x * 64;   // gridDim.x = K/64 = 64
    int n0 = blockIdx.y * 32;   // gridDim.y = N/32 = 256
    int t = threadIdx.x;        // 256 threads
#pragma unroll
    for (int i = 0; i < 8; ++i) {
        int idx = i * 256 + t;
        int kk = idx >> 5, nl = idx & 31;
        sh[kk * 33 + nl] = x[(size_t)(k0 + kk) * N_DIM + n0 + nl];
    }
    __syncthreads();
#pragma unroll
    for (int j = 0; j < 8; ++j) {
        int idx = j * 256 + t;
        int nl = idx >> 6, kk = idx & 63;
        int n = n0 + nl;
        int k = k0 + kk;
        size_t dst = ((size_t)(k >> 5) * N_DIM + n) * 32 + (k & 31);
        g_Xh[dst] = __half_as_ushort(__float2half_rn(sh[kk * 33 + nl]));
    }
}

// ---------------------------------------------------------------------------
// Main GEMM: out = W(fp16) * x(fp16), fp32 accumulate. K = 4096.
// CTA 128x256x32, 16 warps (4m x 4n), warp tile 32x64, 4-stage cp.async.
// ---------------------------------------------------------------------------
__global__ void __launch_bounds__(THREADS, 1) gemm_kernel(float* __restrict__ out) {
    extern __shared__ __align__(128) char smem[];
    const uint32_t sb = smem_u32(smem);
    const int tid = threadIdx.x;
    const int lane = tid & 31;
    const int wid = tid >> 5;
    const int wm = (wid & 3) * 32;    // warp m offset (0/32/64/96)
    const int wn = (wid >> 2) * 64;   // warp n offset (0/64/128/192)
    const int m0 = blockIdx.x * BM;
    const int n0 = blockIdx.y * BN;

    float acc[2][8][4];
#pragma unroll
    for (int i = 0; i < 2; ++i)
#pragma unroll
        for (int j = 0; j < 8; ++j)
#pragma unroll
            for (int r = 0; r < 4; ++r) acc[i][j][r] = 0.f;

    // per-lane ldmatrix byte offsets (validated addressing from R1 kernel)
    const uint32_t a_lane_off =
        (uint32_t)((wm + (lane & 15)) * ROW_B + (lane >> 4) * 16);
    const uint32_t b_lane_off =
        (uint32_t)((wn + (lane & 7) + ((lane >> 4) & 1) * 8) * ROW_B +
                   ((lane >> 3) & 1) * 16);

    auto load_stage = [&](int kt, int s) {
        const char* asrc = (const char*)g_Wh + ((size_t)kt * M_DIM + m0) * 64;
        const char* bsrc = (const char*)g_Xh + ((size_t)kt * N_DIM + n0) * 64;
        uint32_t As = sb + s * STAGE_B;
        uint32_t Bs = As + A_STAGE_B;
        {   // A: 512 x 16B chunks, one per thread
            int c = tid;
            cp16(As + (uint32_t)((c >> 2) * ROW_B + (c & 3) * 16), asrc + (size_t)c * 16);
        }
#pragma unroll
        for (int j = 0; j < 2; ++j) {   // B: 1024 x 16B chunks
            int c = tid + j * THREADS;
            cp16(Bs + (uint32_t)((c >> 2) * ROW_B + (c & 3) * 16), bsrc + (size_t)c * 16);
        }
    };

    auto compute = [&](int s) {
        const uint32_t As = sb + s * STAGE_B + a_lane_off;
        const uint32_t Bs = sb + s * STAGE_B + A_STAGE_B + b_lane_off;
#pragma unroll
        for (int ks = 0; ks < 2; ++ks) {
            uint32_t a[2][4], b[4][4];
#pragma unroll
            for (int mi = 0; mi < 2; ++mi)
                ldsm4(a[mi], As + mi * (16 * ROW_B) + ks * 32);
#pragma unroll
            for (int nj = 0; nj < 4; ++nj)
                ldsm4(b[nj], Bs + nj * (16 * ROW_B) + ks * 32);
#pragma unroll
            for (int mi = 0; mi < 2; ++mi)
#pragma unroll
                for (int nj = 0; nj < 4; ++nj) {
                    mma16816(acc[mi][2 * nj], a[mi], b[nj][0], b[nj][1]);
                    mma16816(acc[mi][2 * nj + 1], a[mi], b[nj][2], b[nj][3]);
                }
        }
    };

    // prologue: fill 3 stages
#pragma unroll
    for (int s = 0; s < STAGES - 1; ++s) {
        load_stage(s, s);
        CP_COMMIT();
    }

    for (int it = 0; it < ITERS; ++it) {
        CP_WAIT2();            // own groups <= it complete
        __syncthreads();       // cross-thread visibility + smem reuse safety
        if (it + 3 < ITERS) load_stage(it + 3, (it + 3) & (STAGES - 1));
        CP_COMMIT();           // always commit (possibly empty) to keep count math
        compute(it & (STAGES - 1));
    }

    // epilogue: direct fp32 stores (each element owned by exactly one thread)
#pragma unroll
    for (int mi = 0; mi < 2; ++mi) {
        int row = m0 + wm + mi * 16 + (lane >> 2);
#pragma unroll
        for (int ni = 0; ni < 8; ++ni) {
            int col = n0 + wn + ni * 8 + (lane & 3) * 2;
            float2* p0 = reinterpret_cast<float2*>(out + (size_t)row * N_DIM + col);
            float2* p1 = reinterpret_cast<float2*>(out + (size_t)(row + 8) * N_DIM + col);
            *p0 = make_float2(acc[mi][ni][0], acc[mi][ni][1]);
            *p1 = make_float2(acc[mi][ni][2], acc[mi][ni][3]);
        }
    }
}

// ---------------------------------------------------------------------------
// Launch
// ---------------------------------------------------------------------------
extern "C" void kernel_launch(void* const* d_in, const int* in_sizes, int n_in,
                              void* d_out, int out_size) {
    const int*   rows = (const int*)d_in[0];
    const int*   cols = (const int*)d_in[1];
    const float* vals = (const float*)d_in[2];
    const float* x    = (const float*)d_in[3];
    float* out = (float*)d_out;
    int nnz = in_sizes[0];

    clear_kernel<<<2048, 256>>>();
    scatter_kernel<<<(nnz + 255) / 256, 256>>>(rows, cols, vals, nnz);
    packW_kernel<<<(int)(((size_t)M_DIM * K_DIM / 4 + 255) / 256), 256>>>();
    packX_kernel<<<dim3(K_DIM / 64, N_DIM / 32), 256>>>(x);

    static int smem_set = 0;
    if (!smem_set) {
        cudaFuncSetAttribute(gemm_kernel, cudaFuncAttributeMaxDynamicSharedMemorySize,
                             SMEM_TOTAL);
        smem_set = 1;
    }
    gemm_kernel<<<dim3(M_DIM / BM, N_DIM / BN), THREADS, SMEM_TOTAL>>>(out);
}